// round 12
// baseline (speedup 1.0000x reference)
#include <cuda_runtime.h>
#include <math.h>

#define N 1024
#define D 128
#define SPARSE_K 32

typedef unsigned long long u64;

// ---------------- device scratch (no allocations allowed) ----------------
__device__ float g_Q[N * D];
__device__ float g_K[N * D];
__device__ float g_A[N * D];   // z @ W1[:D] + b1
__device__ float g_B[N * D];   // z @ W1[D:]
__device__ float g_S[(size_t)N * N];
__device__ int   g_done;       // attn-completion counter (reset by proj)

__device__ __forceinline__ float neg_inf() { return __int_as_float(0xff800000); }

// ---------------- packed f32x2 helpers ----------------
__device__ __forceinline__ u64 pk2(float lo, float hi) {
    u64 r; asm("mov.b64 %0, {%1, %2};" : "=l"(r) : "f"(lo), "f"(hi)); return r;
}
__device__ __forceinline__ void upk2(float& lo, float& hi, u64 v) {
    asm("mov.b64 {%0, %1}, %2;" : "=f"(lo), "=f"(hi) : "l"(v));
}
__device__ __forceinline__ u64 fma2(u64 a, u64 b, u64 c) {
    u64 r; asm("fma.rn.f32x2 %0, %1, %2, %3;" : "=l"(r) : "l"(a), "l"(b), "l"(c)); return r;
}
__device__ __forceinline__ u64 add2(u64 a, u64 b) {
    u64 r; asm("add.rn.f32x2 %0, %1, %2;" : "=l"(r) : "l"(a), "l"(b)); return r;
}
__device__ __forceinline__ u64 mul2(u64 a, u64 b) {
    u64 r; asm("mul.rn.f32x2 %0, %1, %2;" : "=l"(r) : "l"(a), "l"(b)); return r;
}
__device__ __forceinline__ float tanh_hw(float x) {
    float t; asm("tanh.approx.f32 %0, %1;" : "=f"(t) : "f"(x)); return t;
}

// =====================================================================
// Kernel 1 (fused): [Q | K | A | B] = z @ [Wq | Wk | W1a | W1b] (+ bias)
// 32x64 tiles, SINGLE full-K load, one sync. dynamic smem 51.7KB.
// Also resets g_done for the union kernel.
// =====================================================================
struct SmemProj {
    float Zs[32][132];
    float Ws[128][68];
};
#define PROJ_SMEM_BYTES sizeof(SmemProj)

__global__ __launch_bounds__(256) void proj_fused_kernel(
    const float* __restrict__ z,
    const float* __restrict__ Wq, const float* __restrict__ bq,
    const float* __restrict__ Wk, const float* __restrict__ bk,
    const float* __restrict__ W1, const float* __restrict__ b1)
{
    extern __shared__ __align__(16) char dynsm_p[];
    SmemProj& sm = *(SmemProj*)dynsm_p;

    if (blockIdx.x == 0 && blockIdx.y == 0 && threadIdx.x == 0) g_done = 0;

    int ct = blockIdx.x;           // 0..7
    int which = ct >> 1;
    int j0 = (ct & 1) * 64;
    int i0 = blockIdx.y * 32;

    const float* W; const float* bias; float* out;
    if (which == 0)      { W = Wq;         bias = bq;      out = g_Q; }
    else if (which == 1) { W = Wk;         bias = bk;      out = g_K; }
    else if (which == 2) { W = W1;         bias = b1;      out = g_A; }
    else                 { W = W1 + D * D; bias = nullptr; out = g_B; }

    int tid = threadIdx.x;
    int tx = tid & 15;             // j = j0 + tx + cj*16
    int ty = tid >> 4;             // i = i0 + ty*2 + ri

#pragma unroll
    for (int it = 0; it < 4; it++) {
        int f = tid + it * 256;
        int r = f >> 5, c4 = f & 31;
        *(float4*)&sm.Zs[r][c4 * 4] = *(const float4*)&z[(i0 + r) * D + c4 * 4];
    }
#pragma unroll
    for (int it = 0; it < 8; it++) {
        int f = tid + it * 256;
        int r = f >> 4, c4 = f & 15;
        *(float4*)&sm.Ws[r][c4 * 4] = *(const float4*)&W[r * D + j0 + c4 * 4];
    }
    __syncthreads();

    float acc[2][4];
#pragma unroll
    for (int a = 0; a < 2; a++)
#pragma unroll
        for (int b = 0; b < 4; b++) acc[a][b] = 0.0f;

#pragma unroll 8
    for (int k = 0; k < D; k++) {
        float av[2], bv[4];
#pragma unroll
        for (int ri = 0; ri < 2; ri++) av[ri] = sm.Zs[ty * 2 + ri][k];
#pragma unroll
        for (int cj = 0; cj < 4; cj++) bv[cj] = sm.Ws[k][tx + cj * 16];
#pragma unroll
        for (int ri = 0; ri < 2; ri++)
#pragma unroll
            for (int cj = 0; cj < 4; cj++)
                acc[ri][cj] = fmaf(av[ri], bv[cj], acc[ri][cj]);
    }

    float bb[4] = {0.f, 0.f, 0.f, 0.f};
    if (bias) {
#pragma unroll
        for (int cj = 0; cj < 4; cj++) bb[cj] = bias[j0 + tx + cj * 16];
    }
#pragma unroll
    for (int ri = 0; ri < 2; ri++) {
        int row = i0 + ty * 2 + ri;
#pragma unroll
        for (int cj = 0; cj < 4; cj++)
            out[row * D + j0 + tx + cj * 16] = acc[ri][cj] + bb[cj];
    }
}

// =====================================================================
// Union kernel: 1536 blocks   (R6 dispatch order restored)
//   [0,256)     pair 64x64 tiles (R6 body, 2-chunk, pk2 packing)
//   [256,512)   attn 64x64 tiles (R6 body) + g_done increment
//   [512,1536)  softmax+topk rows, gated on g_done==256
// =====================================================================
struct SmemPair {
    float As[64][68];
    float Bs[64][68];
    float2 w2d[D * 3];     // 0.5*W2 duplicated into both lanes
    float b2s[3];
};
struct SmemAttn {
    float Qs[64][68];
    float Ks[64][68];
};
struct SmemSoft {
    float red[9];
    float cand[256];
    float s_thresh;
};
union SmemUnion {
    SmemPair p;
    SmemAttn a;
    SmemSoft s;
};

__device__ __forceinline__ void pair_body(SmemPair& sm, int bx, int by,
                                          const float* __restrict__ W2,
                                          const float* __restrict__ b2,
                                          float* __restrict__ out)
{
    int tid = threadIdx.x;
    int tx = tid & 15;          // j = j0 + tx + cj*16
    int ty = tid >> 4;          // i = i0 + ty*4 + ri
    int i0 = by * 64;
    int j0 = bx * 64;

    for (int idx = tid; idx < D * 3; idx += 256) {
        float w = 0.5f * W2[idx];
        sm.w2d[idx] = make_float2(w, w);
    }
    if (tid < 3) sm.b2s[tid] = b2[tid];

    const u64 C0 = pk2(0.7978845608028654f, 0.7978845608028654f);
    const u64 C1 = pk2(0.035677408136300125f, 0.035677408136300125f);

    u64 acc[4][2][3];
#pragma unroll
    for (int a = 0; a < 4; a++)
#pragma unroll
        for (int b = 0; b < 2; b++)
#pragma unroll
            for (int c = 0; c < 3; c++) acc[a][b][c] = 0ull;

    for (int kc = 0; kc < D; kc += 64) {
#pragma unroll
        for (int it = 0; it < 4; it++) {
            int f = tid + it * 256;
            int r = f >> 4, c4 = f & 15;
            *(float4*)&sm.As[r][c4 * 4] = *(const float4*)&g_A[(i0 + r) * D + kc + c4 * 4];
            *(float4*)&sm.Bs[r][c4 * 4] = *(const float4*)&g_B[(j0 + r) * D + kc + c4 * 4];
        }
        __syncthreads();

#pragma unroll 1
        for (int k4 = 0; k4 < 16; k4++) {
            float a_[4][4], b_[4][4];
#pragma unroll
            for (int ri = 0; ri < 4; ri++) {
                float4 t = *(const float4*)&sm.As[ty * 4 + ri][k4 * 4];
                a_[ri][0] = t.x; a_[ri][1] = t.y; a_[ri][2] = t.z; a_[ri][3] = t.w;
            }
#pragma unroll
            for (int cj = 0; cj < 4; cj++) {
                float4 t = *(const float4*)&sm.Bs[tx + cj * 16][k4 * 4];
                b_[cj][0] = t.x; b_[cj][1] = t.y; b_[cj][2] = t.z; b_[cj][3] = t.w;
            }
#pragma unroll
            for (int kk = 0; kk < 4; kk++) {
                int d = kc + k4 * 4 + kk;
                u64 w0_2 = *(const u64*)&sm.w2d[d * 3 + 0];
                u64 w1_2 = *(const u64*)&sm.w2d[d * 3 + 1];
                u64 w2_2 = *(const u64*)&sm.w2d[d * 3 + 2];
                u64 bp[2];
                bp[0] = pk2(b_[0][kk], b_[1][kk]);
                bp[1] = pk2(b_[2][kk], b_[3][kk]);
#pragma unroll
                for (int ri = 0; ri < 4; ri++) {
                    u64 a2 = pk2(a_[ri][kk], a_[ri][kk]);
#pragma unroll
                    for (int pj = 0; pj < 2; pj++) {
                        u64 x2 = add2(a2, bp[pj]);
                        u64 u2 = mul2(x2, x2);
                        u64 q2 = fma2(C1, u2, C0);
                        u64 y2 = mul2(x2, q2);
                        float ylo, yhi;
                        upk2(ylo, yhi, y2);
                        u64 t2 = pk2(tanh_hw(ylo), tanh_hw(yhi));
                        u64 g2 = fma2(x2, t2, x2);   // = 2*gelu; W2 pre-halved
                        acc[ri][pj][0] = fma2(g2, w0_2, acc[ri][pj][0]);
                        acc[ri][pj][1] = fma2(g2, w1_2, acc[ri][pj][1]);
                        acc[ri][pj][2] = fma2(g2, w2_2, acc[ri][pj][2]);
                    }
                }
            }
        }
        __syncthreads();
    }

    const size_t OFF = (size_t)N * N;
    float vb0 = sm.b2s[0], vb1 = sm.b2s[1], vb2 = sm.b2s[2];
#pragma unroll
    for (int ri = 0; ri < 4; ri++) {
        int i = i0 + ty * 4 + ri;
#pragma unroll
        for (int pj = 0; pj < 2; pj++) {
            float l0a, l0b, l1a, l1b, l2a, l2b;
            upk2(l0a, l0b, acc[ri][pj][0]);
            upk2(l1a, l1b, acc[ri][pj][1]);
            upk2(l2a, l2b, acc[ri][pj][2]);
#pragma unroll
            for (int h = 0; h < 2; h++) {
                int cj = pj * 2 + h;
                int j = j0 + tx + cj * 16;
                float l0 = (h ? l0b : l0a) + vb0;
                float l1 = (h ? l1b : l1a) + vb1;
                float l2 = (h ? l2b : l2a) + vb2;
                float mm = fmaxf(l0, fmaxf(l1, l2));
                float e0 = __expf(l0 - mm);
                float e1 = __expf(l1 - mm);
                float e2 = __expf(l2 - mm);
                float inv = __fdividef(1.0f, e0 + e1 + e2);
                size_t base = OFF + ((size_t)i * N + j) * 3;
                out[base + 0] = e0 * inv;
                out[base + 1] = e1 * inv;
                out[base + 2] = e2 * inv;
            }
        }
    }
}

__device__ __forceinline__ void attn_body(SmemAttn& sm, int bx, int by,
                                          const float* __restrict__ sd)
{
    int tid = threadIdx.x;
    int tx = tid & 15;
    int ty = tid >> 4;
    int i0 = by * 64;
    int j0 = bx * 64;

    float acc[4][4];
#pragma unroll
    for (int a = 0; a < 4; a++)
#pragma unroll
        for (int b = 0; b < 4; b++) acc[a][b] = 0.0f;

    for (int kc = 0; kc < D; kc += 64) {
#pragma unroll
        for (int it = 0; it < 4; it++) {
            int f = tid + it * 256;
            int r = f >> 4, c4 = f & 15;
            *(float4*)&sm.Qs[r][c4 * 4] = *(const float4*)&g_Q[(i0 + r) * D + kc + c4 * 4];
            *(float4*)&sm.Ks[r][c4 * 4] = *(const float4*)&g_K[(j0 + r) * D + kc + c4 * 4];
        }
        __syncthreads();
#pragma unroll 8
        for (int k = 0; k < 64; k++) {
            float qv[4], kv[4];
#pragma unroll
            for (int ri = 0; ri < 4; ri++) qv[ri] = sm.Qs[ty * 4 + ri][k];
#pragma unroll
            for (int cj = 0; cj < 4; cj++) kv[cj] = sm.Ks[tx + cj * 16][k];
#pragma unroll
            for (int ri = 0; ri < 4; ri++)
#pragma unroll
                for (int cj = 0; cj < 4; cj++)
                    acc[ri][cj] = fmaf(qv[ri], kv[cj], acc[ri][cj]);
        }
        __syncthreads();
    }

    const float SCALE = 0.08838834764831845f;  // 1/sqrt(128)
#pragma unroll
    for (int ri = 0; ri < 4; ri++) {
        int i = i0 + ty * 4 + ri;
#pragma unroll
        for (int cj = 0; cj < 4; cj++) {
            int j = j0 + tx + cj * 16;
            size_t idx = (size_t)i * N + j;
            g_S[idx] = acc[ri][cj] * SCALE * __expf(-sd[idx]);
        }
    }

    // signal completion: order my writes, then count this block
    __threadfence();
    __syncthreads();
    if (tid == 0) atomicAdd(&g_done, 1);
}

__device__ __forceinline__ float warp_max(float x) {
#pragma unroll
    for (int o = 16; o; o >>= 1) x = fmaxf(x, __shfl_xor_sync(0xffffffffu, x, o));
    return x;
}

__device__ __forceinline__ void softmax_body(SmemSoft& sm, int row,
                                             float* __restrict__ out_adj)
{
    int tid = threadIdx.x;
    int w = tid >> 5, l = tid & 31;

    // wait until all 256 attn blocks have committed g_S
    if (tid == 0) {
        while (atomicAdd(&g_done, 0) < 256) { __nanosleep(128); }
    }
    __syncthreads();

    const float* s = g_S + (size_t)row * N;
    float v[4];
#pragma unroll
    for (int q = 0; q < 4; q++) v[q] = __ldcg(&s[tid + q * 256]);

    float m = warp_max(fmaxf(fmaxf(v[0], v[1]), fmaxf(v[2], v[3])));
    if (l == 0) sm.red[w] = m;
    __syncthreads();
    if (tid < 32) {
        float y = (l < 8) ? sm.red[l] : neg_inf();
        y = warp_max(y);
        if (l == 0) sm.red[8] = y;
    }
    __syncthreads();
    m = sm.red[8];

    float p[4], ls = 0.0f;
#pragma unroll
    for (int q = 0; q < 4; q++) { p[q] = __expf(v[q] - m); ls += p[q]; }
#pragma unroll
    for (int o = 16; o; o >>= 1) ls += __shfl_xor_sync(0xffffffffu, ls, o);
    if (l == 0) sm.red[w] = ls;
    __syncthreads();
    if (tid < 32) {
        float y = (l < 8) ? sm.red[l] : 0.0f;
#pragma unroll
        for (int o = 4; o; o >>= 1) y += __shfl_xor_sync(0xffffffffu, y, o);
        if (l == 0) sm.red[8] = y;
    }
    __syncthreads();
    float Z = sm.red[8];

    float ww[4];
#pragma unroll
    for (int q = 0; q < 4; q++) ww[q] = v[q];
    for (int it = 0; it < SPARSE_K; it++) {
        float lm = fmaxf(fmaxf(ww[0], ww[1]), fmaxf(ww[2], ww[3]));
        float gm = warp_max(lm);
#pragma unroll
        for (int q = 0; q < 4; q++) if (ww[q] == gm) ww[q] = neg_inf();
        if (l == 0) sm.cand[w * 32 + it] = gm;
    }
    __syncthreads();

    if (tid < 32) {
        float c[8];
#pragma unroll
        for (int q = 0; q < 8; q++) c[q] = sm.cand[l + q * 32];
        float gm = neg_inf();
        for (int it = 0; it < SPARSE_K; it++) {
            float lm = c[0];
#pragma unroll
            for (int q = 1; q < 8; q++) lm = fmaxf(lm, c[q]);
            gm = warp_max(lm);
#pragma unroll
            for (int q = 0; q < 8; q++) if (c[q] == gm) c[q] = neg_inf();
        }
        if (l == 0) sm.s_thresh = gm;
    }
    __syncthreads();
    float thresh = sm.s_thresh;

    float invZ = __fdividef(1.0f, Z);
#pragma unroll
    for (int q = 0; q < 4; q++) {
        int j = tid + q * 256;
        out_adj[(size_t)row * N + j] = (v[q] >= thresh) ? p[q] * invZ : 0.0f;
    }
}

__global__ __launch_bounds__(256, 2) void fused_main_kernel(
    const float* __restrict__ sd,
    const float* __restrict__ W2, const float* __restrict__ b2,
    float* __restrict__ out)
{
    __shared__ __align__(16) SmemUnion sm;
    int b = blockIdx.x;
    if (b < 256) {
        pair_body(sm.p, b & 15, b >> 4, W2, b2, out);     // long pole first
    } else if (b < 512) {
        int ab = b - 256;
        attn_body(sm.a, ab & 15, ab >> 4, sd);            // fills pair tail
    } else {
        softmax_body(sm.s, b - 512, out);                 // gated on attn done
    }
}

// =====================================================================
// launch
// =====================================================================
extern "C" void kernel_launch(void* const* d_in, const int* in_sizes, int n_in,
                              void* d_out, int out_size)
{
    const float* z   = (const float*)d_in[0];
    const float* sd  = (const float*)d_in[1];
    const float* Wq  = (const float*)d_in[2];
    const float* bq  = (const float*)d_in[3];
    const float* Wk  = (const float*)d_in[4];
    const float* bk  = (const float*)d_in[5];
    const float* W1  = (const float*)d_in[6];
    const float* b1  = (const float*)d_in[7];
    const float* W2  = (const float*)d_in[8];
    const float* b2  = (const float*)d_in[9];
    float* out = (float*)d_out;

    (void)in_sizes; (void)n_in; (void)out_size;

    static bool attr_set = false;
    if (!attr_set) {
        cudaFuncSetAttribute(proj_fused_kernel,
                             cudaFuncAttributeMaxDynamicSharedMemorySize,
                             (int)PROJ_SMEM_BYTES);
        attr_set = true;
    }

    // resets g_done, then computes Q/K/A/B
    proj_fused_kernel<<<dim3(8, 32), 256, PROJ_SMEM_BYTES>>>(z, Wq, bq, Wk, bk, W1, b1);

    // pair (0-255) long pole; attn (256-511) fills tail, unblocks softmax (512-1535)
    fused_main_kernel<<<1536, 256>>>(sd, W2, b2, out);
}

// round 13
// speedup vs baseline: 1.1007x; 1.1007x over previous
#include <cuda_runtime.h>
#include <math.h>

#define N 1024
#define D 128
#define SPARSE_K 32

typedef unsigned long long u64;

// ---------------- device scratch (no allocations allowed) ----------------
__device__ float g_Q[N * D];
__device__ float g_K[N * D];
__device__ float g_A[N * D];   // z @ W1[:D] + b1
__device__ float g_B[N * D];   // z @ W1[D:]
__device__ float g_S[(size_t)N * N];

__device__ __forceinline__ float neg_inf() { return __int_as_float(0xff800000); }

// ---------------- packed f32x2 helpers ----------------
__device__ __forceinline__ u64 pk2(float lo, float hi) {
    u64 r; asm("mov.b64 %0, {%1, %2};" : "=l"(r) : "f"(lo), "f"(hi)); return r;
}
__device__ __forceinline__ void upk2(float& lo, float& hi, u64 v) {
    asm("mov.b64 {%0, %1}, %2;" : "=f"(lo), "=f"(hi) : "l"(v));
}
__device__ __forceinline__ u64 fma2(u64 a, u64 b, u64 c) {
    u64 r; asm("fma.rn.f32x2 %0, %1, %2, %3;" : "=l"(r) : "l"(a), "l"(b), "l"(c)); return r;
}
__device__ __forceinline__ u64 add2(u64 a, u64 b) {
    u64 r; asm("add.rn.f32x2 %0, %1, %2;" : "=l"(r) : "l"(a), "l"(b)); return r;
}
__device__ __forceinline__ u64 mul2(u64 a, u64 b) {
    u64 r; asm("mul.rn.f32x2 %0, %1, %2;" : "=l"(r) : "l"(a), "l"(b)); return r;
}
__device__ __forceinline__ float tanh_hw(float x) {
    float t; asm("tanh.approx.f32 %0, %1;" : "=f"(t) : "f"(x)); return t;
}

// =====================================================================
// Kernel 1 (fused): [Q | K | A | B] = z @ [Wq | Wk | W1a | W1b] (+ bias)
// 32x64 tiles, SINGLE full-K load, one sync. dynamic smem 51.7KB.
// (verified ~6.5us in R11 ncu arithmetic)
// =====================================================================
struct SmemProj {
    float Zs[32][132];
    float Ws[128][68];
};
#define PROJ_SMEM_BYTES sizeof(SmemProj)

__global__ __launch_bounds__(256) void proj_fused_kernel(
    const float* __restrict__ z,
    const float* __restrict__ Wq, const float* __restrict__ bq,
    const float* __restrict__ Wk, const float* __restrict__ bk,
    const float* __restrict__ W1, const float* __restrict__ b1)
{
    extern __shared__ __align__(16) char dynsm_p[];
    SmemProj& sm = *(SmemProj*)dynsm_p;

    int ct = blockIdx.x;           // 0..7
    int which = ct >> 1;
    int j0 = (ct & 1) * 64;
    int i0 = blockIdx.y * 32;

    const float* W; const float* bias; float* out;
    if (which == 0)      { W = Wq;         bias = bq;      out = g_Q; }
    else if (which == 1) { W = Wk;         bias = bk;      out = g_K; }
    else if (which == 2) { W = W1;         bias = b1;      out = g_A; }
    else                 { W = W1 + D * D; bias = nullptr; out = g_B; }

    int tid = threadIdx.x;
    int tx = tid & 15;             // j = j0 + tx + cj*16
    int ty = tid >> 4;             // i = i0 + ty*2 + ri

#pragma unroll
    for (int it = 0; it < 4; it++) {
        int f = tid + it * 256;
        int r = f >> 5, c4 = f & 31;
        *(float4*)&sm.Zs[r][c4 * 4] = *(const float4*)&z[(i0 + r) * D + c4 * 4];
    }
#pragma unroll
    for (int it = 0; it < 8; it++) {
        int f = tid + it * 256;
        int r = f >> 4, c4 = f & 15;
        *(float4*)&sm.Ws[r][c4 * 4] = *(const float4*)&W[r * D + j0 + c4 * 4];
    }
    __syncthreads();

    float acc[2][4];
#pragma unroll
    for (int a = 0; a < 2; a++)
#pragma unroll
        for (int b = 0; b < 4; b++) acc[a][b] = 0.0f;

#pragma unroll 8
    for (int k = 0; k < D; k++) {
        float av[2], bv[4];
#pragma unroll
        for (int ri = 0; ri < 2; ri++) av[ri] = sm.Zs[ty * 2 + ri][k];
#pragma unroll
        for (int cj = 0; cj < 4; cj++) bv[cj] = sm.Ws[k][tx + cj * 16];
#pragma unroll
        for (int ri = 0; ri < 2; ri++)
#pragma unroll
            for (int cj = 0; cj < 4; cj++)
                acc[ri][cj] = fmaf(av[ri], bv[cj], acc[ri][cj]);
    }

    float bb[4] = {0.f, 0.f, 0.f, 0.f};
    if (bias) {
#pragma unroll
        for (int cj = 0; cj < 4; cj++) bb[cj] = bias[j0 + tx + cj * 16];
    }
#pragma unroll
    for (int ri = 0; ri < 2; ri++) {
        int row = i0 + ty * 2 + ri;
#pragma unroll
        for (int cj = 0; cj < 4; cj++)
            out[row * D + j0 + tx + cj * 16] = acc[ri][cj] + bb[cj];
    }
}

// =====================================================================
// Union kernel: EXACT R6 — 512 blocks; [0,256) pair, [256,512) attn
// =====================================================================
struct SmemPair {
    float As[64][68];
    float Bs[64][68];
    float2 w2d[D * 3];     // 0.5*W2 duplicated into both lanes
    float b2s[3];
};
struct SmemAttn {
    float Qs[64][68];
    float Ks[64][68];
};
union SmemUnion {
    SmemPair p;
    SmemAttn a;
};

__device__ __forceinline__ void pair_body(SmemPair& sm, int bx, int by,
                                          const float* __restrict__ W2,
                                          const float* __restrict__ b2,
                                          float* __restrict__ out)
{
    int tid = threadIdx.x;
    int tx = tid & 15;          // j = j0 + tx + cj*16
    int ty = tid >> 4;          // i = i0 + ty*4 + ri
    int i0 = by * 64;
    int j0 = bx * 64;

    for (int idx = tid; idx < D * 3; idx += 256) {
        float w = 0.5f * W2[idx];
        sm.w2d[idx] = make_float2(w, w);
    }
    if (tid < 3) sm.b2s[tid] = b2[tid];

    const u64 C0 = pk2(0.7978845608028654f, 0.7978845608028654f);
    const u64 C1 = pk2(0.035677408136300125f, 0.035677408136300125f);

    u64 acc[4][2][3];
#pragma unroll
    for (int a = 0; a < 4; a++)
#pragma unroll
        for (int b = 0; b < 2; b++)
#pragma unroll
            for (int c = 0; c < 3; c++) acc[a][b][c] = 0ull;

    for (int kc = 0; kc < D; kc += 64) {
#pragma unroll
        for (int it = 0; it < 4; it++) {
            int f = tid + it * 256;
            int r = f >> 4, c4 = f & 15;
            *(float4*)&sm.As[r][c4 * 4] = *(const float4*)&g_A[(i0 + r) * D + kc + c4 * 4];
            *(float4*)&sm.Bs[r][c4 * 4] = *(const float4*)&g_B[(j0 + r) * D + kc + c4 * 4];
        }
        __syncthreads();

#pragma unroll 1
        for (int k4 = 0; k4 < 16; k4++) {
            float a_[4][4], b_[4][4];
#pragma unroll
            for (int ri = 0; ri < 4; ri++) {
                float4 t = *(const float4*)&sm.As[ty * 4 + ri][k4 * 4];
                a_[ri][0] = t.x; a_[ri][1] = t.y; a_[ri][2] = t.z; a_[ri][3] = t.w;
            }
#pragma unroll
            for (int cj = 0; cj < 4; cj++) {
                float4 t = *(const float4*)&sm.Bs[tx + cj * 16][k4 * 4];
                b_[cj][0] = t.x; b_[cj][1] = t.y; b_[cj][2] = t.z; b_[cj][3] = t.w;
            }
#pragma unroll
            for (int kk = 0; kk < 4; kk++) {
                int d = kc + k4 * 4 + kk;
                u64 w0_2 = *(const u64*)&sm.w2d[d * 3 + 0];
                u64 w1_2 = *(const u64*)&sm.w2d[d * 3 + 1];
                u64 w2_2 = *(const u64*)&sm.w2d[d * 3 + 2];
                u64 bp[2];
                bp[0] = pk2(b_[0][kk], b_[1][kk]);
                bp[1] = pk2(b_[2][kk], b_[3][kk]);
#pragma unroll
                for (int ri = 0; ri < 4; ri++) {
                    u64 a2 = pk2(a_[ri][kk], a_[ri][kk]);
#pragma unroll
                    for (int pj = 0; pj < 2; pj++) {
                        u64 x2 = add2(a2, bp[pj]);
                        u64 u2 = mul2(x2, x2);
                        u64 q2 = fma2(C1, u2, C0);
                        u64 y2 = mul2(x2, q2);
                        float ylo, yhi;
                        upk2(ylo, yhi, y2);
                        u64 t2 = pk2(tanh_hw(ylo), tanh_hw(yhi));
                        u64 g2 = fma2(x2, t2, x2);   // = 2*gelu; W2 pre-halved
                        acc[ri][pj][0] = fma2(g2, w0_2, acc[ri][pj][0]);
                        acc[ri][pj][1] = fma2(g2, w1_2, acc[ri][pj][1]);
                        acc[ri][pj][2] = fma2(g2, w2_2, acc[ri][pj][2]);
                    }
                }
            }
        }
        __syncthreads();
    }

    const size_t OFF = (size_t)N * N;
    float vb0 = sm.b2s[0], vb1 = sm.b2s[1], vb2 = sm.b2s[2];
#pragma unroll
    for (int ri = 0; ri < 4; ri++) {
        int i = i0 + ty * 4 + ri;
#pragma unroll
        for (int pj = 0; pj < 2; pj++) {
            float l0a, l0b, l1a, l1b, l2a, l2b;
            upk2(l0a, l0b, acc[ri][pj][0]);
            upk2(l1a, l1b, acc[ri][pj][1]);
            upk2(l2a, l2b, acc[ri][pj][2]);
#pragma unroll
            for (int h = 0; h < 2; h++) {
                int cj = pj * 2 + h;
                int j = j0 + tx + cj * 16;
                float l0 = (h ? l0b : l0a) + vb0;
                float l1 = (h ? l1b : l1a) + vb1;
                float l2 = (h ? l2b : l2a) + vb2;
                float mm = fmaxf(l0, fmaxf(l1, l2));
                float e0 = __expf(l0 - mm);
                float e1 = __expf(l1 - mm);
                float e2 = __expf(l2 - mm);
                float inv = __fdividef(1.0f, e0 + e1 + e2);
                size_t base = OFF + ((size_t)i * N + j) * 3;
                out[base + 0] = e0 * inv;
                out[base + 1] = e1 * inv;
                out[base + 2] = e2 * inv;
            }
        }
    }
}

__device__ __forceinline__ void attn_body(SmemAttn& sm, int bx, int by,
                                          const float* __restrict__ sd)
{
    int tid = threadIdx.x;
    int tx = tid & 15;
    int ty = tid >> 4;
    int i0 = by * 64;
    int j0 = bx * 64;

    float acc[4][4];
#pragma unroll
    for (int a = 0; a < 4; a++)
#pragma unroll
        for (int b = 0; b < 4; b++) acc[a][b] = 0.0f;

    for (int kc = 0; kc < D; kc += 64) {
#pragma unroll
        for (int it = 0; it < 4; it++) {
            int f = tid + it * 256;
            int r = f >> 4, c4 = f & 15;
            *(float4*)&sm.Qs[r][c4 * 4] = *(const float4*)&g_Q[(i0 + r) * D + kc + c4 * 4];
            *(float4*)&sm.Ks[r][c4 * 4] = *(const float4*)&g_K[(j0 + r) * D + kc + c4 * 4];
        }
        __syncthreads();
#pragma unroll 8
        for (int k = 0; k < 64; k++) {
            float qv[4], kv[4];
#pragma unroll
            for (int ri = 0; ri < 4; ri++) qv[ri] = sm.Qs[ty * 4 + ri][k];
#pragma unroll
            for (int cj = 0; cj < 4; cj++) kv[cj] = sm.Ks[tx + cj * 16][k];
#pragma unroll
            for (int ri = 0; ri < 4; ri++)
#pragma unroll
                for (int cj = 0; cj < 4; cj++)
                    acc[ri][cj] = fmaf(qv[ri], kv[cj], acc[ri][cj]);
        }
        __syncthreads();
    }

    const float SCALE = 0.08838834764831845f;  // 1/sqrt(128)
#pragma unroll
    for (int ri = 0; ri < 4; ri++) {
        int i = i0 + ty * 4 + ri;
#pragma unroll
        for (int cj = 0; cj < 4; cj++) {
            int j = j0 + tx + cj * 16;
            size_t idx = (size_t)i * N + j;
            g_S[idx] = acc[ri][cj] * SCALE * __expf(-sd[idx]);
        }
    }
}

__global__ __launch_bounds__(256, 2) void fused_main_kernel(
    const float* __restrict__ sd,
    const float* __restrict__ W2, const float* __restrict__ b2,
    float* __restrict__ out)
{
    __shared__ __align__(16) SmemUnion sm;
    int b = blockIdx.x;
    if (b < 256) {
        pair_body(sm.p, b & 15, b >> 4, W2, b2, out);
    } else {
        int ab = b - 256;
        attn_body(sm.a, ab & 15, ab >> 4, sd);
    }
}

// =====================================================================
// Kernel 3: row softmax + top-32 scatter (separate launch, R6 version)
// =====================================================================
__device__ __forceinline__ float warp_max(float x) {
#pragma unroll
    for (int o = 16; o; o >>= 1) x = fmaxf(x, __shfl_xor_sync(0xffffffffu, x, o));
    return x;
}

__global__ __launch_bounds__(256) void softmax_topk_kernel(float* __restrict__ out_adj)
{
    __shared__ float red[9];
    __shared__ float cand[256];
    __shared__ float s_thresh;

    int row = blockIdx.x;
    int tid = threadIdx.x;
    int w = tid >> 5, l = tid & 31;
    const float* s = g_S + (size_t)row * N;

    float v[4];
#pragma unroll
    for (int q = 0; q < 4; q++) v[q] = s[tid + q * 256];

    float m = warp_max(fmaxf(fmaxf(v[0], v[1]), fmaxf(v[2], v[3])));
    if (l == 0) red[w] = m;
    __syncthreads();
    if (tid < 32) {
        float y = (l < 8) ? red[l] : neg_inf();
        y = warp_max(y);
        if (l == 0) red[8] = y;
    }
    __syncthreads();
    m = red[8];

    float p[4], ls = 0.0f;
#pragma unroll
    for (int q = 0; q < 4; q++) { p[q] = __expf(v[q] - m); ls += p[q]; }
#pragma unroll
    for (int o = 16; o; o >>= 1) ls += __shfl_xor_sync(0xffffffffu, ls, o);
    if (l == 0) red[w] = ls;
    __syncthreads();
    if (tid < 32) {
        float y = (l < 8) ? red[l] : 0.0f;
#pragma unroll
        for (int o = 4; o; o >>= 1) y += __shfl_xor_sync(0xffffffffu, y, o);
        if (l == 0) red[8] = y;
    }
    __syncthreads();
    float Z = red[8];

    float ww[4];
#pragma unroll
    for (int q = 0; q < 4; q++) ww[q] = v[q];
    for (int it = 0; it < SPARSE_K; it++) {
        float lm = fmaxf(fmaxf(ww[0], ww[1]), fmaxf(ww[2], ww[3]));
        float gm = warp_max(lm);
#pragma unroll
        for (int q = 0; q < 4; q++) if (ww[q] == gm) ww[q] = neg_inf();
        if (l == 0) cand[w * 32 + it] = gm;
    }
    __syncthreads();

    if (tid < 32) {
        float c[8];
#pragma unroll
        for (int q = 0; q < 8; q++) c[q] = cand[l + q * 32];
        float gm = neg_inf();
        for (int it = 0; it < SPARSE_K; it++) {
            float lm = c[0];
#pragma unroll
            for (int q = 1; q < 8; q++) lm = fmaxf(lm, c[q]);
            gm = warp_max(lm);
#pragma unroll
            for (int q = 0; q < 8; q++) if (c[q] == gm) c[q] = neg_inf();
        }
        if (l == 0) s_thresh = gm;
    }
    __syncthreads();
    float thresh = s_thresh;

    float invZ = __fdividef(1.0f, Z);
#pragma unroll
    for (int q = 0; q < 4; q++) {
        int j = tid + q * 256;
        out_adj[(size_t)row * N + j] = (v[q] >= thresh) ? p[q] * invZ : 0.0f;
    }
}

// =====================================================================
// launch
// =====================================================================
extern "C" void kernel_launch(void* const* d_in, const int* in_sizes, int n_in,
                              void* d_out, int out_size)
{
    const float* z   = (const float*)d_in[0];
    const float* sd  = (const float*)d_in[1];
    const float* Wq  = (const float*)d_in[2];
    const float* bq  = (const float*)d_in[3];
    const float* Wk  = (const float*)d_in[4];
    const float* bk  = (const float*)d_in[5];
    const float* W1  = (const float*)d_in[6];
    const float* b1  = (const float*)d_in[7];
    const float* W2  = (const float*)d_in[8];
    const float* b2  = (const float*)d_in[9];
    float* out = (float*)d_out;

    (void)in_sizes; (void)n_in; (void)out_size;

    static bool attr_set = false;
    if (!attr_set) {
        cudaFuncSetAttribute(proj_fused_kernel,
                             cudaFuncAttributeMaxDynamicSharedMemorySize,
                             (int)PROJ_SMEM_BYTES);
        attr_set = true;
    }

    proj_fused_kernel<<<dim3(8, 32), 256, PROJ_SMEM_BYTES>>>(z, Wq, bq, Wk, bk, W1, b1);

    // pair (0-255) + attn (256-511), R6 structure
    fused_main_kernel<<<512, 256>>>(sd, W2, b2, out);

    softmax_topk_kernel<<<N, 256>>>(out);   // adjacency -> out[0 : N*N]
}